// round 13
// baseline (speedup 1.0000x reference)
#include <cuda_runtime.h>
#include <cstdint>
#include <cstddef>

#define Bsz   64
#define Tlen  512
#define HID   1024
#define VOC   128
#define GRID  128
#define CPC   8          // hidden columns owned per CTA
#define NTHR  512
#define KSPL  4          // k-split groups
#define KRNG  256        // k-rows per group
#define CHUNK_K 32       // k-rows per cp.async chunk (8KB)
#define NCHUNK  8        // chunks per group (256/32)
#define FSTRIDE 32       // flag padding: one 128B line per flag
#define KC    128        // W_o rows per head chunk

// ---------------- persistent device scratch (no allocations allowed) ----------
__device__ float g_hT[HID * Bsz];                       // h, transposed [k][b]
__device__ float g_rhT[HID * Bsz];                      // r*h, transposed [k][b]
__device__ float g_hist[(size_t)Tlen * HID * Bsz];      // [t][k][b]  (134 MB)
__device__ __align__(128) unsigned g_flags[GRID * FSTRIDE];   // zero-init

// ---------------- helpers -----------------------------------------------------
__device__ __forceinline__ void ffma2(unsigned long long &acc,
                                      unsigned long long a,
                                      unsigned long long b) {
    asm volatile("fma.rn.f32x2 %0, %1, %2, %0;" : "+l"(acc) : "l"(a), "l"(b));
}

__device__ __forceinline__ void unpack2(unsigned long long v, float &lo, float &hi) {
    asm("mov.b64 {%0, %1}, %2;" : "=f"(lo), "=f"(hi) : "l"(v));
}

__device__ __forceinline__ float sigmoidf_(float x) {
    return 1.0f / (1.0f + __expf(-x));
}

// distributed-flag grid barrier: release-store own (padded) flag,
// 128 threads each acquire-poll one (padded) flag.
__device__ __forceinline__ void gbar(unsigned stamp) {
    __syncthreads();
    if (threadIdx.x == 0) {
        asm volatile("st.global.release.gpu.u32 [%0], %1;"
                     :: "l"(&g_flags[blockIdx.x * FSTRIDE]), "r"(stamp) : "memory");
    }
    if (threadIdx.x < GRID) {
        unsigned v;
        do {
            asm volatile("ld.global.acquire.gpu.u32 %0, [%1];"
                         : "=r"(v) : "l"(&g_flags[threadIdx.x * FSTRIDE]) : "memory");
        } while (v < stamp);
    }
    __syncthreads();
}

// copy one 8KB chunk (32 k-rows x 64 batch floats = 2048 f) gmem -> smem.
// 128 threads of a group participate; 64B contiguous per thread.
__device__ __forceinline__ void copy_chunk(float* dst, const float* src, int r128) {
    uint32_t s = (uint32_t)__cvta_generic_to_shared(dst) + r128 * 64;
    const float* g = src + r128 * 16;
    #pragma unroll
    for (int i = 0; i < 4; ++i) {
        asm volatile("cp.async.cg.shared.global [%0], [%1], 16;"
                     :: "r"(s + i * 16), "l"(g + i * 4) : "memory");
    }
    asm volatile("cp.async.commit_group;" ::: "memory");
}

__device__ __forceinline__ void wait_cp0() {
    asm volatile("cp.async.wait_group 0;" ::: "memory");
}

__device__ __forceinline__ void named_bar(int id) {
    asm volatile("bar.sync %0, 128;" :: "r"(id) : "memory");
}

// ---------------- persistent fused GRU + head kernel ----------------------------
__global__ void __launch_bounds__(NTHR, 1)
gru_step_kernel(const int* __restrict__ X,
                const float* __restrict__ Wr_x, const float* __restrict__ b_r,
                const float* __restrict__ Wz_x, const float* __restrict__ b_z,
                const float* __restrict__ Wh_x, const float* __restrict__ b_h,
                const float* __restrict__ Wr_h, const float* __restrict__ Wz_h,
                const float* __restrict__ Wh_h,
                const float* __restrict__ W_o,  const float* __restrict__ b_o,
                float* __restrict__ out)
{
    extern __shared__ float smem[];
    float* sA   = smem;                    // [k][c] -> {wr,wz}         (64 KB)
    float* sB   = sA + HID * CPC * 2;      // [k][c] -> {wh,wh}         (64 KB)
    float* ring = sB + HID * CPC * 2;      // 4 groups x 2 slots x 2048 (64 KB)
    float* red  = ring + KSPL * 2 * 2048;  // k-split reduction buffer  (16 KB)
    int*   tok  = (int*)(red + 4096);      // tokens for this step (64)
    float* bias = (float*)(tok + Bsz);     // b_r | b_z | b_h (8 each)

    const int tid = threadIdx.x;
    const int cb  = blockIdx.x;
    const int c0  = cb * CPC;

    unsigned bstamp = g_flags[cb * FSTRIDE];

    // ---- preload weight slices into smem ----
    for (int idx = tid; idx < HID * CPC; idx += NTHR) {
        int k = idx / CPC, c = idx % CPC;
        sA[idx * 2 + 0] = Wr_h[k * HID + c0 + c];
        sA[idx * 2 + 1] = Wz_h[k * HID + c0 + c];
        float wh = Wh_h[k * HID + c0 + c];
        sB[idx * 2 + 0] = wh; sB[idx * 2 + 1] = wh;
    }
    if (tid < CPC)          bias[tid] = b_r[c0 + tid];
    else if (tid < 2 * CPC) bias[tid] = b_z[c0 + tid - CPC];
    else if (tid < 3 * CPC) bias[tid] = b_h[c0 + tid - 2 * CPC];

    // zero this CTA's columns of h (h0 = 0); must be re-done every launch
    if (tid < CPC * Bsz)
        g_hT[c0 * Bsz + tid] = 0.0f;

    gbar(++bstamp);

    // GEMM mapping: 4 kg groups x (16 bq x 8 c); each thread accumulates
    // 4 batch rows (two f32x2 pairs) for its column over KRNG k-rows.
    const int kg    = tid >> 7;           // 0..3
    const int r128  = tid & 127;
    const int bq    = r128 >> 3;          // 0..15 (batch quad)
    const int c     = r128 & 7;           // 0..7  (column within CTA)
    const int kbase = kg * KRNG;
    float* myring   = ring + kg * 2 * 2048;
    const int barid = 1 + kg;

    // postproc mapping: one (b, col) per thread; h and z live in registers
    const int b    = tid & 63;
    const int cq   = tid >> 6;            // 0..7
    const int ccol = c0 + cq;
    float h_prev = 0.0f;
    float zv_reg = 0.0f;

    for (int t = 0; t < Tlen; ++t) {
        if (tid < Bsz) tok[tid] = X[tid * Tlen + t];
        __syncthreads();

        // x-gathers for this step (consumed in postprocs, hidden under GEMM)
        const int tk = tok[b];
        const float xr = __ldg(&Wr_x[tk * HID + ccol]);
        const float xz = __ldg(&Wz_x[tk * HID + ccol]);
        const float xh = __ldg(&Wh_x[tk * HID + ccol]);

        // ======================= Phase A: r,z = h @ [Wr_h|Wz_h] ================
        unsigned long long aR0 = 0, aR1 = 0, aZ0 = 0, aZ1 = 0;
        {
            const float* gsrc = g_hT + kbase * Bsz;
            copy_chunk(myring, gsrc, r128);                      // chunk 0
            #pragma unroll 1
            for (int ch = 0; ch < NCHUNK; ++ch) {
                wait_cp0();
                named_bar(barid);
                if (ch + 1 < NCHUNK)
                    copy_chunk(myring + ((ch + 1) & 1) * 2048,
                               gsrc + (ch + 1) * 2048, r128);
                const float* hs  = myring + (ch & 1) * 2048 + bq * 4;
                const float* wpb = sA + ((kbase + ch * CHUNK_K) * CPC + c) * 2;
                #pragma unroll
                for (int kl = 0; kl < CHUNK_K; ++kl) {
                    ulonglong2 hv = *(const ulonglong2*)(hs + kl * Bsz);
                    float2 wv = *(const float2*)(wpb + kl * CPC * 2);
                    unsigned long long wr2, wz2;
                    asm("mov.b64 %0, {%1, %1};" : "=l"(wr2) : "f"(wv.x));
                    asm("mov.b64 %0, {%1, %1};" : "=l"(wz2) : "f"(wv.y));
                    ffma2(aR0, hv.x, wr2);
                    ffma2(aR1, hv.y, wr2);
                    ffma2(aZ0, hv.x, wz2);
                    ffma2(aZ1, hv.y, wz2);
                }
            }
        }
        {   // write k-split partials: red[((kg*64 + b)*8 + c)*2 + {r,z}]
            float r0, r1, r2, r3, z0, z1, z2, z3;
            unpack2(aR0, r0, r1); unpack2(aR1, r2, r3);
            unpack2(aZ0, z0, z1); unpack2(aZ1, z2, z3);
            float* rp = red + ((kg * Bsz + bq * 4) * CPC + c) * 2;
            rp[0] = r0; rp[1] = z0; rp += CPC * 2;
            rp[0] = r1; rp[1] = z1; rp += CPC * 2;
            rp[0] = r2; rp[1] = z2; rp += CPC * 2;
            rp[0] = r3; rp[1] = z3;
        }
        __syncthreads();
        {   // gates + r*h for this thread's (b, ccol)
            float sR = 0.0f, sZ = 0.0f;
            #pragma unroll
            for (int g = 0; g < KSPL; ++g) {
                sR += red[((g * Bsz + b) * CPC + cq) * 2 + 0];
                sZ += red[((g * Bsz + b) * CPC + cq) * 2 + 1];
            }
            float rv = sigmoidf_(sR + xr + bias[cq]);
            zv_reg   = sigmoidf_(sZ + xz + bias[CPC + cq]);
            g_rhT[ccol * Bsz + b] = rv * h_prev;
        }
        gbar(++bstamp);

        // ======================= Phase B: htilde = (r*h) @ Wh_h ================
        unsigned long long aH0 = 0, aH1 = 0;
        {
            const float* gsrc = g_rhT + kbase * Bsz;
            copy_chunk(myring, gsrc, r128);
            #pragma unroll 1
            for (int ch = 0; ch < NCHUNK; ++ch) {
                wait_cp0();
                named_bar(barid);
                if (ch + 1 < NCHUNK)
                    copy_chunk(myring + ((ch + 1) & 1) * 2048,
                               gsrc + (ch + 1) * 2048, r128);
                const float* hs  = myring + (ch & 1) * 2048 + bq * 4;
                const float* wpb = sB + ((kbase + ch * CHUNK_K) * CPC + c) * 2;
                #pragma unroll
                for (int kl = 0; kl < CHUNK_K; ++kl) {
                    ulonglong2 hv = *(const ulonglong2*)(hs + kl * Bsz);
                    unsigned long long w =
                        *(const unsigned long long*)(wpb + kl * CPC * 2);
                    ffma2(aH0, hv.x, w);
                    ffma2(aH1, hv.y, w);
                }
            }
        }
        {
            float h0, h1, h2, h3;
            unpack2(aH0, h0, h1); unpack2(aH1, h2, h3);
            float* rp = red + (kg * Bsz + bq * 4) * CPC + c;
            rp[0] = h0; rp[CPC] = h1; rp[2 * CPC] = h2; rp[3 * CPC] = h3;
        }
        __syncthreads();
        {   // h update + history write for this thread's (b, ccol)
            float sH = 0.0f;
            #pragma unroll
            for (int g = 0; g < KSPL; ++g)
                sH += red[(g * Bsz + b) * CPC + cq];
            float ht = tanhf(sH + xh + bias[2 * CPC + cq]);
            float hn = zv_reg * h_prev + (1.0f - zv_reg) * ht;
            h_prev = hn;
            g_hT[ccol * Bsz + b] = hn;
            g_hist[((size_t)t * HID + ccol) * Bsz + b] = hn;
        }
        gbar(++bstamp);
    }

    // ================= fused output head: 4 timesteps per CTA ==================
    // out[b][t][v] = hist[t][:][b] . W_o[:,v] + b_o ; reuses sA region for W_o.
    {
        float* swo = smem;                  // KC x VOC chunk of W_o (64 KB)
        const int hb = tid >> 3;            // 0..63
        const int v0 = (tid & 7) * 16;      // 16 vocab cols per thread

        for (int tt = 0; tt < 4; ++tt) {
            const int t = cb * 4 + tt;

            unsigned long long acc[8];
            #pragma unroll
            for (int i = 0; i < 8; ++i) acc[i] = 0ull;

            for (int kc = 0; kc < HID; kc += KC) {
                __syncthreads();
                for (int i = tid; i < KC * VOC; i += NTHR)
                    swo[i] = W_o[kc * VOC + i];
                __syncthreads();

                const float* hp = g_hist + ((size_t)t * HID + kc) * Bsz + hb;
                #pragma unroll 1
                for (int kk = 0; kk < KC; kk += 8) {
                    float hv[8];
                    #pragma unroll
                    for (int u = 0; u < 8; ++u) hv[u] = __ldcg(hp + (kk + u) * Bsz);
                    #pragma unroll
                    for (int u = 0; u < 8; ++u) {
                        unsigned long long hs;
                        asm("mov.b64 %0, {%1, %1};" : "=l"(hs) : "f"(hv[u]));
                        const float* wrow = swo + (kk + u) * VOC + v0;
                        #pragma unroll
                        for (int q = 0; q < 4; ++q) {
                            ulonglong2 w = *(const ulonglong2*)(wrow + q * 4);
                            ffma2(acc[q * 2 + 0], hs, w.x);
                            ffma2(acc[q * 2 + 1], hs, w.y);
                        }
                    }
                }
            }

            float* op = out + ((size_t)hb * Tlen + t) * VOC + v0;
            #pragma unroll
            for (int q = 0; q < 8; ++q) {
                float lo, hi;
                unpack2(acc[q], lo, hi);
                int v = v0 + q * 2;
                op[q * 2 + 0] = lo + b_o[v + 0];
                op[q * 2 + 1] = hi + b_o[v + 1];
            }
        }
    }
}

// ---------------- launch ------------------------------------------------------
extern "C" void kernel_launch(void* const* d_in, const int* in_sizes, int n_in,
                              void* d_out, int out_size)
{
    const int*   X    = (const int*)  d_in[0];
    const float* Wr_x = (const float*)d_in[1];
    const float* Wr_h = (const float*)d_in[2];
    const float* b_r  = (const float*)d_in[3];
    const float* Wz_x = (const float*)d_in[4];
    const float* Wz_h = (const float*)d_in[5];
    const float* b_z  = (const float*)d_in[6];
    const float* Wh_x = (const float*)d_in[7];
    const float* Wh_h = (const float*)d_in[8];
    const float* b_h  = (const float*)d_in[9];
    const float* W_o  = (const float*)d_in[10];
    const float* b_o  = (const float*)d_in[11];
    float* out = (float*)d_out;

    // smem: sA 16384f + sB 16384f + ring 16384f + red 4096f + tok 64i + bias 32f
    //       (~208.4 KB; head phase reuses the sA region)
    size_t smem1 = (size_t)(HID * CPC * 2 + HID * CPC * 2 + KSPL * 2 * 2048 + 4096)
                 * sizeof(float) + Bsz * sizeof(int) + 32 * sizeof(float);

    cudaFuncSetAttribute(gru_step_kernel,
                         cudaFuncAttributeMaxDynamicSharedMemorySize, (int)smem1);

    gru_step_kernel<<<GRID, NTHR, smem1>>>(X, Wr_x, b_r, Wz_x, b_z, Wh_x, b_h,
                                           Wr_h, Wz_h, Wh_h, W_o, b_o, out);
}

// round 14
// speedup vs baseline: 1.0656x; 1.0656x over previous
#include <cuda_runtime.h>
#include <cstdint>
#include <cstddef>

#define Bsz   64
#define Tlen  512
#define HID   1024
#define VOC   128
#define GRID  128
#define CPC   8          // hidden columns owned per CTA
#define NTHR  512
#define KSPL  4          // k-split groups
#define KRNG  256        // k-rows per group
#define CHUNK_K 16       // k-rows per cp.async chunk (4KB)
#define NCHUNK  16       // chunks per group (256/16)
#define FSTRIDE 32       // flag padding: one 128B line per flag
#define KC    128        // W_o rows per head chunk
#define XSTR  12         // xg row stride (floats): 16B-aligned, 4-way-conflict max

// ---------------- persistent device scratch (no allocations allowed) ----------
__device__ float g_hT[HID * Bsz];                       // h, transposed [k][b]
__device__ float g_rhT[HID * Bsz];                      // r*h, transposed [k][b]
__device__ float g_hist[(size_t)Tlen * HID * Bsz];      // [t][k][b]  (134 MB)
__device__ __align__(128) unsigned g_flags[GRID * FSTRIDE];   // zero-init

// ---------------- helpers -----------------------------------------------------
__device__ __forceinline__ void ffma2(unsigned long long &acc,
                                      unsigned long long a,
                                      unsigned long long b) {
    asm volatile("fma.rn.f32x2 %0, %1, %2, %0;" : "+l"(acc) : "l"(a), "l"(b));
}

__device__ __forceinline__ void unpack2(unsigned long long v, float &lo, float &hi) {
    asm("mov.b64 {%0, %1}, %2;" : "=f"(lo), "=f"(hi) : "l"(v));
}

__device__ __forceinline__ float sigmoidf_(float x) {
    return 1.0f / (1.0f + __expf(-x));
}

// distributed-flag grid barrier: release-store own (padded) flag,
// 128 threads each acquire-poll one (padded) flag.
__device__ __forceinline__ void gbar(unsigned stamp) {
    __syncthreads();
    if (threadIdx.x == 0) {
        asm volatile("st.global.release.gpu.u32 [%0], %1;"
                     :: "l"(&g_flags[blockIdx.x * FSTRIDE]), "r"(stamp) : "memory");
    }
    if (threadIdx.x < GRID) {
        unsigned v;
        do {
            asm volatile("ld.global.acquire.gpu.u32 %0, [%1];"
                         : "=r"(v) : "l"(&g_flags[threadIdx.x * FSTRIDE]) : "memory");
        } while (v < stamp);
    }
    __syncthreads();
}

// copy one 4KB chunk (16 k-rows x 64 batch floats = 1024 f) gmem -> smem.
// 128 threads of a group participate; 32B contiguous per thread.
__device__ __forceinline__ void copy_chunk(float* dst, const float* src, int r128) {
    uint32_t s = (uint32_t)__cvta_generic_to_shared(dst) + r128 * 32;
    const float* g = src + r128 * 8;
    asm volatile("cp.async.cg.shared.global [%0], [%1], 16;"
                 :: "r"(s), "l"(g) : "memory");
    asm volatile("cp.async.cg.shared.global [%0], [%1], 16;"
                 :: "r"(s + 16), "l"(g + 4) : "memory");
    asm volatile("cp.async.commit_group;" ::: "memory");
}

__device__ __forceinline__ void wait_cp0() {
    asm volatile("cp.async.wait_group 0;" ::: "memory");
}

__device__ __forceinline__ void named_bar(int id) {
    asm volatile("bar.sync %0, 128;" :: "r"(id) : "memory");
}

// ---------------- persistent fused GRU + head kernel ----------------------------
__global__ void __launch_bounds__(NTHR, 1)
gru_step_kernel(const int* __restrict__ X,
                const float* __restrict__ Wr_x, const float* __restrict__ b_r,
                const float* __restrict__ Wz_x, const float* __restrict__ b_z,
                const float* __restrict__ Wh_x, const float* __restrict__ b_h,
                const float* __restrict__ Wr_h, const float* __restrict__ Wz_h,
                const float* __restrict__ Wh_h,
                const float* __restrict__ W_o,  const float* __restrict__ b_o,
                float* __restrict__ out)
{
    extern __shared__ float smem[];
    float* sA   = smem;                    // [k][c] -> {wr,wr,wz,wz}   (128 KB)
    float* sB   = sA + HID * CPC * 4;      // [k][c] -> wh (non-dup)    (32 KB)
    float* ring = sB + HID * CPC;          // 4 groups x 2 slots x 1024 (32 KB)
    float* red  = ring + KSPL * 2 * 1024;  // k-split reduction buffer  (16 KB)
    float* xg   = red + 4096;              // staged x-gathers (3x64x12) (9 KB)
    int*   tok  = (int*)(xg + 3 * Bsz * XSTR);   // tokens (prefetched)
    float* bias = (float*)(tok + Bsz);     // b_r | b_z | b_h (8 each)

    const int tid = threadIdx.x;
    const int cb  = blockIdx.x;
    const int c0  = cb * CPC;

    unsigned bstamp = g_flags[cb * FSTRIDE];

    // ---- preload weight slices into smem ----
    for (int idx = tid; idx < HID * CPC; idx += NTHR) {
        int k = idx / CPC, c = idx % CPC;
        float wr = Wr_h[k * HID + c0 + c];
        float wz = Wz_h[k * HID + c0 + c];
        sA[idx * 4 + 0] = wr; sA[idx * 4 + 1] = wr;
        sA[idx * 4 + 2] = wz; sA[idx * 4 + 3] = wz;
        sB[idx] = Wh_h[k * HID + c0 + c];
    }
    if (tid < CPC)          bias[tid] = b_r[c0 + tid];
    else if (tid < 2 * CPC) bias[tid] = b_z[c0 + tid - CPC];
    else if (tid < 3 * CPC) bias[tid] = b_h[c0 + tid - 2 * CPC];

    // zero this CTA's columns of h (h0 = 0); must be re-done every launch
    if (tid < CPC * Bsz)
        g_hT[c0 * Bsz + tid] = 0.0f;

    // prefetch tokens for step 0
    if (tid < Bsz) tok[tid] = X[tid * Tlen];

    gbar(++bstamp);

    // GEMM mapping: 4 kg groups x (16 bq x 8 c); each thread accumulates
    // 4 batch rows (two f32x2 pairs) for its column over KRNG k-rows.
    const int kg    = tid >> 7;           // 0..3
    const int r128  = tid & 127;
    const int bq    = r128 >> 3;          // 0..15 (batch quad)
    const int c     = r128 & 7;           // 0..7  (column within CTA)
    const int kbase = kg * KRNG;
    float* myring   = ring + kg * 2 * 1024;
    const int barid = 1 + kg;

    // postproc mapping: one (b, col) per thread; h and z live in registers
    const int b    = tid & 63;
    const int cq   = tid >> 6;            // 0..7
    const int ccol = c0 + cq;
    float h_prev = 0.0f;
    float zv_reg = 0.0f;

    for (int t = 0; t < Tlen; ++t) {
        // coalesced x-gather for this step (tok prefetched last step; the
        // trailing __syncthreads of gbar orders it). Consumed in postprocs,
        // ordered by the red-buffer __syncthreads.
        if (tid < 384) {
            int m  = tid >> 7;             // 0: Wr_x, 1: Wz_x, 2: Wh_x
            int r  = tid & 127;
            int gb = r >> 1;               // batch row 0..63
            int hf = (r & 1) * 4;          // float4 half of the 8 columns
            const float* W = (m == 0) ? Wr_x : (m == 1) ? Wz_x : Wh_x;
            float4 v = *(const float4*)&W[tok[gb] * HID + c0 + hf];
            *(float4*)&xg[m * Bsz * XSTR + gb * XSTR + hf] = v;
        }

        // ======================= Phase A: r,z = h @ [Wr_h|Wz_h] ================
        unsigned long long aR0 = 0, aR1 = 0, aZ0 = 0, aZ1 = 0;
        {
            const float* gsrc = g_hT + kbase * Bsz;
            copy_chunk(myring, gsrc, r128);                      // chunk 0
            #pragma unroll 1
            for (int ch = 0; ch < NCHUNK; ++ch) {
                wait_cp0();
                named_bar(barid);
                if (ch + 1 < NCHUNK)
                    copy_chunk(myring + ((ch + 1) & 1) * 1024,
                               gsrc + (ch + 1) * 1024, r128);
                const float* hs  = myring + (ch & 1) * 1024 + bq * 4;
                const float* wpb = sA + ((kbase + ch * CHUNK_K) * CPC + c) * 4;
                #pragma unroll
                for (int kl = 0; kl < CHUNK_K; ++kl) {
                    ulonglong2 hv = *(const ulonglong2*)(hs + kl * Bsz);
                    ulonglong2 w  = *(const ulonglong2*)(wpb + kl * CPC * 4);
                    ffma2(aR0, hv.x, w.x);
                    ffma2(aR1, hv.y, w.x);
                    ffma2(aZ0, hv.x, w.y);
                    ffma2(aZ1, hv.y, w.y);
                }
            }
        }
        {   // write k-split partials: red[((kg*64 + b)*8 + c)*2 + {r,z}]
            float r0, r1, r2, r3, z0, z1, z2, z3;
            unpack2(aR0, r0, r1); unpack2(aR1, r2, r3);
            unpack2(aZ0, z0, z1); unpack2(aZ1, z2, z3);
            float* rp = red + ((kg * Bsz + bq * 4) * CPC + c) * 2;
            rp[0] = r0; rp[1] = z0; rp += CPC * 2;
            rp[0] = r1; rp[1] = z1; rp += CPC * 2;
            rp[0] = r2; rp[1] = z2; rp += CPC * 2;
            rp[0] = r3; rp[1] = z3;
        }
        __syncthreads();
        {   // gates + r*h for this thread's (b, ccol)
            float sR = 0.0f, sZ = 0.0f;
            #pragma unroll
            for (int g = 0; g < KSPL; ++g) {
                sR += red[((g * Bsz + b) * CPC + cq) * 2 + 0];
                sZ += red[((g * Bsz + b) * CPC + cq) * 2 + 1];
            }
            float rv = sigmoidf_(sR + xg[b * XSTR + cq] + bias[cq]);
            zv_reg   = sigmoidf_(sZ + xg[Bsz * XSTR + b * XSTR + cq]
                                 + bias[CPC + cq]);
            g_rhT[ccol * Bsz + b] = rv * h_prev;
        }
        gbar(++bstamp);

        // ======================= Phase B: htilde = (r*h) @ Wh_h ================
        unsigned long long aH0 = 0, aH1 = 0;
        {
            const float* gsrc = g_rhT + kbase * Bsz;
            copy_chunk(myring, gsrc, r128);
            #pragma unroll 1
            for (int ch = 0; ch < NCHUNK; ++ch) {
                wait_cp0();
                named_bar(barid);
                if (ch + 1 < NCHUNK)
                    copy_chunk(myring + ((ch + 1) & 1) * 1024,
                               gsrc + (ch + 1) * 1024, r128);
                const float* hs  = myring + (ch & 1) * 1024 + bq * 4;
                const float* wpb = sB + (kbase + ch * CHUNK_K) * CPC + c;
                #pragma unroll
                for (int kl = 0; kl < CHUNK_K; ++kl) {
                    ulonglong2 hv = *(const ulonglong2*)(hs + kl * Bsz);
                    float ws = wpb[kl * CPC];
                    unsigned long long wpk;
                    asm("mov.b64 %0, {%1, %1};" : "=l"(wpk) : "f"(ws));
                    ffma2(aH0, hv.x, wpk);
                    ffma2(aH1, hv.y, wpk);
                }
            }
        }
        {
            float h0, h1, h2, h3;
            unpack2(aH0, h0, h1); unpack2(aH1, h2, h3);
            float* rp = red + (kg * Bsz + bq * 4) * CPC + c;
            rp[0] = h0; rp[CPC] = h1; rp[2 * CPC] = h2; rp[3 * CPC] = h3;
        }
        __syncthreads();
        {   // h update + history write for this thread's (b, ccol)
            float sH = 0.0f;
            #pragma unroll
            for (int g = 0; g < KSPL; ++g)
                sH += red[(g * Bsz + b) * CPC + cq];
            float ht = tanhf(sH + xg[2 * Bsz * XSTR + b * XSTR + cq]
                             + bias[2 * CPC + cq]);
            float hn = zv_reg * h_prev + (1.0f - zv_reg) * ht;
            h_prev = hn;
            g_hT[ccol * Bsz + b] = hn;
            g_hist[((size_t)t * HID + ccol) * Bsz + b] = hn;
        }
        // prefetch tokens for step t+1 (all reads of tok for step t are done:
        // every thread passed the phase-A->B gbar after the top-of-step gather)
        if (tid < Bsz) {
            int tn = (t + 1 < Tlen) ? t + 1 : t;
            tok[tid] = X[tid * Tlen + tn];
        }
        gbar(++bstamp);
    }

    // ================= fused output head: 4 timesteps per CTA ==================
    // out[b][t][v] = hist[t][:][b] . W_o[:,v] + b_o ; reuses sA region for W_o.
    {
        float* swo = smem;                  // KC x VOC chunk of W_o (64 KB)
        const int hb = tid >> 3;            // 0..63
        const int v0 = (tid & 7) * 16;      // 16 vocab cols per thread

        for (int tt = 0; tt < 4; ++tt) {
            const int t = cb * 4 + tt;

            unsigned long long acc[8];
            #pragma unroll
            for (int i = 0; i < 8; ++i) acc[i] = 0ull;

            for (int kc = 0; kc < HID; kc += KC) {
                __syncthreads();
                for (int i = tid; i < KC * VOC; i += NTHR)
                    swo[i] = W_o[kc * VOC + i];
                __syncthreads();

                const float* hp = g_hist + ((size_t)t * HID + kc) * Bsz + hb;
                #pragma unroll 1
                for (int kk = 0; kk < KC; kk += 8) {
                    float hv[8];
                    #pragma unroll
                    for (int u = 0; u < 8; ++u) hv[u] = __ldcg(hp + (kk + u) * Bsz);
                    #pragma unroll
                    for (int u = 0; u < 8; ++u) {
                        unsigned long long hs;
                        asm("mov.b64 %0, {%1, %1};" : "=l"(hs) : "f"(hv[u]));
                        const float* wrow = swo + (kk + u) * VOC + v0;
                        #pragma unroll
                        for (int q = 0; q < 4; ++q) {
                            ulonglong2 w = *(const ulonglong2*)(wrow + q * 4);
                            ffma2(acc[q * 2 + 0], hs, w.x);
                            ffma2(acc[q * 2 + 1], hs, w.y);
                        }
                    }
                }
            }

            float* op = out + ((size_t)hb * Tlen + t) * VOC + v0;
            #pragma unroll
            for (int q = 0; q < 8; ++q) {
                float lo, hi;
                unpack2(acc[q], lo, hi);
                int v = v0 + q * 2;
                op[q * 2 + 0] = lo + b_o[v + 0];
                op[q * 2 + 1] = hi + b_o[v + 1];
            }
        }
    }
}

// ---------------- launch ------------------------------------------------------
extern "C" void kernel_launch(void* const* d_in, const int* in_sizes, int n_in,
                              void* d_out, int out_size)
{
    const int*   X    = (const int*)  d_in[0];
    const float* Wr_x = (const float*)d_in[1];
    const float* Wr_h = (const float*)d_in[2];
    const float* b_r  = (const float*)d_in[3];
    const float* Wz_x = (const float*)d_in[4];
    const float* Wz_h = (const float*)d_in[5];
    const float* b_z  = (const float*)d_in[6];
    const float* Wh_x = (const float*)d_in[7];
    const float* Wh_h = (const float*)d_in[8];
    const float* b_h  = (const float*)d_in[9];
    const float* W_o  = (const float*)d_in[10];
    const float* b_o  = (const float*)d_in[11];
    float* out = (float*)d_out;

    // smem: sA 32768f + sB 8192f + ring 8192f + red 4096f + xg 2304f
    //       + tok 64i + bias 32f  (~222.6 KB)
    size_t smem1 = (size_t)(HID * CPC * 4 + HID * CPC + KSPL * 2 * 1024
                            + 4096 + 3 * Bsz * XSTR) * sizeof(float)
                 + Bsz * sizeof(int) + 32 * sizeof(float);

    cudaFuncSetAttribute(gru_step_kernel,
                         cudaFuncAttributeMaxDynamicSharedMemorySize, (int)smem1);

    gru_step_kernel<<<GRID, NTHR, smem1>>>(X, Wr_x, b_r, Wz_x, b_z, Wh_x, b_h,
                                           Wr_h, Wz_h, Wh_h, W_o, b_o, out);
}